// round 15
// baseline (speedup 1.0000x reference)
#include <cuda_runtime.h>
#include <math.h>

#define PI_F 3.14159265358979323846f
#define BB 4
#define NJ 9216
#define IPB 4     // i-points per block (each i gets 2 warps)
#define QCAP 64   // per-warp candidate stack
#define RBMAX 21.12f        // global bound on rb = 1.3195*max(hw,hl)+1e-3, hw,hl<=16
#define NC6 6
#define NCELLS 36
#define CSZ_INV (1.0f / 43.0f)   // cell size 43 > max coarse radius 42.24

// Binning structures (valid points only, sorted by cell) — the ONLY point arrays.
__device__ int    g_startA[BB][NCELLS + 1];
__device__ float2 g_sYX[BB * NJ];   // (y,x)
__device__ float2 g_sRA[BB * NJ];   // (r_bound, angle)
__device__ float4 g_sP2[BB * NJ];   // (cos a, sin a, 1/hw, 1/hl)
__device__ float2 g_sWL[BB * NJ];   // (wv, lv)
__device__ int    g_iPk[BB * NJ];   // (sortedPos << 14) | localIdx, cell-sorted i-list
__device__ int    g_iNum[BB];
__device__ unsigned int g_ctr;      // block-arrival counter for fused reduction

__device__ __forceinline__ float pow10f(float x) {
    float x2 = x * x;
    float x4 = x2 * x2;
    float x8 = x4 * x4;
    return x8 * x2;
}

// t^(-0.1) via MUFU lg2/ex2
__device__ __forceinline__ float powm01f(float t) {
    float l, r;
    asm("lg2.approx.f32 %0, %1;" : "=f"(l) : "f"(t));
    l = -0.1f * l;
    asm("ex2.approx.f32 %0, %1;" : "=f"(r) : "f"(l));
    return r;
}

// Fused prep+bin: one block per batch. Pass 1 counts cells (cheap loads),
// prefix in shared, pass 2 recomputes full geometry and scatters directly
// into the sorted arrays.
__global__ __launch_bounds__(1024) void prepbin_kernel(
    const float* __restrict__ cc, const int* __restrict__ mask,
    float* __restrict__ out, int P, int out_size)
{
    __shared__ int cCnt[NCELLS], iCnt[NCELLS];
    __shared__ int cStart[NCELLS + 1], cOff[NCELLS];
    __shared__ int iStart[NCELLS], iOff[NCELLS];
    const int b = blockIdx.x;
    const int tid = threadIdx.x;

    if (b == 0 && tid == 0) g_ctr = 0;   // reset arrival counter for fused reduction
    if (tid < NCELLS) { cCnt[tid] = 0; iCnt[tid] = 0; cOff[tid] = 0; iOff[tid] = 0; }
    __syncthreads();

    // pass 1: count (loads only mask, y, x)
    for (int t = tid; t < NJ; t += 1024) {
        int idx = b * NJ + t;
        if (mask[idx] != 0) {
            float y = fminf(fmaxf(cc[(long)idx * 5 + 0], 0.f), 256.f);
            float x = fminf(fmaxf(cc[(long)idx * 5 + 1], 0.f), 256.f);
            int cy = min((int)(y * CSZ_INV), NC6 - 1);
            int cx = min((int)(x * CSZ_INV), NC6 - 1);
            int cell = cy * NC6 + cx;
            atomicAdd(&cCnt[cell], 1);
            if (t < P) atomicAdd(&iCnt[cell], 1);
        } else if (t < P) {
            int oidx = b * P + t;
            if (oidx < out_size) out[oidx] = 0.f;   // masked i-point: energy = 0
        }
    }
    __syncthreads();

    // prefix
    if (tid == 0) {
        int acc = 0, iacc = 0;
        for (int c = 0; c < NCELLS; c++) {
            cStart[c] = acc;  acc  += cCnt[c];
            iStart[c] = iacc; iacc += iCnt[c];
        }
        cStart[NCELLS] = acc;
        g_iNum[b] = iacc;
        for (int c = 0; c <= NCELLS; c++) g_startA[b][c] = cStart[c];
    }
    __syncthreads();

    // pass 2: full geometry + direct scatter into sorted arrays
    for (int t = tid; t < NJ; t += 1024) {
        int idx = b * NJ + t;
        if (mask[idx] == 0) continue;
        const float* p = cc + (long)idx * 5;
        float y  = fminf(fmaxf(p[0], 0.f), 256.f);
        float x  = fminf(fmaxf(p[1], 0.f), 256.f);
        float wv = fminf(fmaxf(p[2], 2.f), 32.f);
        float lv = fminf(fmaxf(p[3], 2.f), 32.f);
        float a  = p[4];
        a = a - floorf(a / PI_F) * PI_F;          // jnp.mod(a, pi)
        float sa, ca;
        sincosf(a, &sa, &ca);
        float hw = 0.5f * wv, hl = 0.5f * lv;
        // superellipse p=10 radius bound: r <= 2^(1/2 - 1/10) * max(hw,hl)
        float rb = 1.3195080f * fmaxf(hw, hl) + 1e-3f;

        int cy = min((int)(y * CSZ_INV), NC6 - 1);
        int cx = min((int)(x * CSZ_INV), NC6 - 1);
        int cell = cy * NC6 + cx;
        int slot = cStart[cell] + atomicAdd(&cOff[cell], 1);
        int gs = b * NJ + slot;
        g_sYX[gs] = make_float2(y, x);
        g_sRA[gs] = make_float2(rb, a);
        g_sP2[gs] = make_float4(ca, sa, 1.f / hw, 1.f / hl);
        g_sWL[gs] = make_float2(wv, lv);
        if (t < P) {
            int islot = iStart[cell] + atomicAdd(&iOff[cell], 1);
            g_iPk[b * NJ + islot] = (slot << 14) | t;   // slot,t < 9216 < 2^14
        }
    }
}

// Dense evaluation of one queued candidate (global sorted index gs).
__device__ __forceinline__ void dense_eval(
    int gs, float yi, float xi, float rib, float ai,
    float cai, float sai, float ihw, float ihl,
    float& omax, float& amin)
{
    float2 yx = g_sYX[gs];
    float2 ra = g_sRA[gs];
    float dy = yi - yx.x;
    float dx = xi - yx.y;
    float d2 = fmaf(dy, dy, dx * dx);   // > 0 guaranteed by coarse gate

    if (d2 < 1024.f) {                  // align: dist < 32 (strict)
        float ad = ai - ra.y;           // both in [0, pi)
        if (ad < 0.f) ad += PI_F;       // mod pi
        ad = fminf(ad, PI_F - ad);
        float al = fminf(fmaxf(fmaf(ad, 4.f / PI_F, -1.f), -1.f), 1.f);
        amin = fminf(amin, al);
    }

    float rsum = rib + ra.x;
    if (d2 < rsum * rsum) {             // refined overlap gate
        float d2c  = fmaxf(d2, 1e-12f);
        float rinv = rsqrtf(d2c);
        float dist = d2c * rinv;
        float ct = dy * rinv;           // cos(theta)
        float st = dx * rinv;           // sin(theta)
        float4 c2 = g_sP2[gs];
        float ci = fabsf(fmaf(ct, cai,  st * sai)) + 1e-8f;
        float si = fabsf(fmaf(st, cai, -(ct * sai))) + 1e-8f;
        float cj = fabsf(fmaf(ct, c2.x,  st * c2.y)) + 1e-8f;
        float sj = fabsf(fmaf(st, c2.x, -(ct * c2.y))) + 1e-8f;
        float ti = pow10f(ci * ihw)  + pow10f(si * ihl);
        float tj = pow10f(cj * c2.z) + pow10f(sj * c2.w);
        float ri = powm01f(ti);
        float rj = powm01f(tj);
        float ov = 1.f - __fdividef(dist, ri + rj + 1e-8f);
        omax = fmaxf(omax, fminf(fmaxf(ov, 0.f), 1.f));
    }
}

// 2 warps per i-point; sub==0 warp also computes the 7-term map energy lane-parallel.
// Last arriving block performs the final per-batch/total reduction.
__global__ __launch_bounds__(256) void pair_kernel(
    const float* __restrict__ pem, const float* __restrict__ mwm,
    const float* __restrict__ mlm, const float* __restrict__ mam,
    const float* __restrict__ comb_w, const float* __restrict__ comb_b,
    float* __restrict__ out, int P, int out_size)
{
    __shared__ int   sQ[8][QCAP];
    __shared__ float sOmax[8], sAmin[8];
    __shared__ unsigned int sIsLast;
    __shared__ double sh[256];

    const int bpb  = P / IPB;
    const int b    = blockIdx.x / bpb;
    const int wid  = threadIdx.x >> 5;
    const int sub  = wid & 1;                              // which half of the chunks
    const int k    = (blockIdx.x % bpb) * IPB + (wid >> 1);  // sorted i index
    const int lane = threadIdx.x & 31;
    const unsigned laneLT = (1u << lane) - 1u;

    const bool active = (k < g_iNum[b]);
    float yi = 0.f, xi = 0.f, rib = 0.f, ai = 0.f;
    float cai = 1.f, sai = 0.f, ihw = 1.f, ihl = 1.f;
    float coarse2 = 0.f;
    int   i = 0, gp = 0;

    if (active) {
        int pk = g_iPk[b * NJ + k];
        int pos = pk >> 14;
        i = pk & 16383;
        gp = b * NJ + pos;
        float2 yx1 = g_sYX[gp];
        float2 ra1 = g_sRA[gp];
        float4 p2  = g_sP2[gp];
        yi = yx1.x; xi = yx1.y; rib = ra1.x; ai = ra1.y;
        cai = p2.x; sai = p2.y; ihw = p2.z; ihl = p2.w;
        float cr = rib + RBMAX;
        coarse2 = fmaxf(cr * cr, 1024.f);
    }

    // ---- lane-parallel map energy (sub==0 warp only) ----
    float emap = 0.f;
    if (active && sub == 0) {
        float2 wl = g_sWL[gp];                 // (wv, lv)
        float val = 0.f;
        float yc = fminf(yi, 255.f);           // yi,xi in [0,256]
        float xc = fminf(xi, 255.f);
        float y0 = floorf(yc), x0 = floorf(xc);
        int iy0 = (int)y0, ix0 = (int)x0;
        int iy1 = min(iy0 + 1, 255), ix1 = min(ix0 + 1, 255);
        float wy = yc - y0, wx = xc - x0;
        if (lane < 28) {
            int t = (lane < 4) ? 0 : ((lane < 12) ? 1 : ((lane < 20) ? 2 : 3));
            int rel = (t == 0) ? lane : (lane - 4 - (t - 1) * 8);
            int ch  = (t == 0) ? 0 : (rel >> 2);
            int corner = rel & 3;
            int iy = (corner & 2) ? iy1 : iy0;
            int ix = (corner & 1) ? ix1 : ix0;
            float wgt = ((corner & 2) ? wy : 1.f - wy) * ((corner & 1) ? wx : 1.f - wx);
            const float* mp;
            float m;
            if      (t == 0) { mp = pem; m = 0.f;   }
            else if (t == 1) { mp = mwm; m = wl.x;  }
            else if (t == 2) { mp = mlm; m = wl.y;  }
            else             { mp = mam; m = ai;    }
            int cidx = 0;
            if (t == 3) {                       // cyclic trilinear, vmin=0 vmax=pi
                float c = (m - 0.f) / PI_F * 32.f - 0.5f;
                c = c - floorf(c * (1.f / 32.f)) * 32.f;
                float c0 = floorf(c);
                float cw = c - c0;
                int i0 = ((int)c0) & 31, i1 = (i0 + 1) & 31;
                cidx = ch ? i1 : i0;
                wgt *= ch ? cw : 1.f - cw;
            } else if (t > 0) {                 // non-cyclic, vmin=2 vmax=32
                float c = (m - 2.f) / 30.f * 32.f - 0.5f;
                c = fminf(fmaxf(c, 0.f), 31.f);
                float c0 = floorf(c);
                float cw = c - c0;
                int i0 = (int)c0, i1 = min(i0 + 1, 31);
                cidx = ch ? i1 : i0;
                wgt *= ch ? cw : 1.f - cw;
            }
            val = __ldg(mp + cidx * 65536 + iy * 256 + ix) * wgt * __ldg(comb_w + t);
        } else if (lane == 28) {
            float area = 1.f - 2.f * fminf(fmaxf(wl.x * wl.y * (1.f / 256.f), 0.f), 1.f);
            val = area * __ldg(comb_w + 6) + __ldg(comb_b);
        }
        #pragma unroll
        for (int off = 16; off; off >>= 1)
            val += __shfl_xor_sync(0xffffffffu, val, off);
        emap = val;
    }

    float omax = 0.f;   // overlap contributions are >= 0; self/invalid give 0
    float amin = 0.f;   // align matrix always contains 0 entries (self pair)
    int   qn   = 0;     // per-warp candidate-stack depth (warp-uniform)

    if (active) {
        int cy = min((int)(yi * CSZ_INV), NC6 - 1);
        int cx = min((int)(xi * CSZ_INV), NC6 - 1);
        int r0 = max(cy - 1, 0), r1 = min(cy + 1, NC6 - 1);
        int c0 = max(cx - 1, 0), c1 = min(cx + 1, NC6 - 1);

        for (int row = r0; row <= r1; row++) {
            // cells row*6+c0 .. row*6+c1 are contiguous -> single range
            int lo = g_startA[b][row * NC6 + c0];
            int hi = g_startA[b][row * NC6 + c1 + 1];
            for (int base = lo + sub * 32; base < hi; base += 64) {
                int s = base + lane;
                int sc = min(s, hi - 1);              // clamp load, gate with (s<hi)
                float2 q = g_sYX[b * NJ + sc];
                float dy = yi - q.x;
                float dx = xi - q.y;
                float d2 = fmaf(dy, dy, dx * dx);
                bool cand = (s < hi) && (d2 > 0.f) && (d2 < coarse2);

                unsigned m = __ballot_sync(0xffffffffu, cand);
                if (cand) sQ[wid][qn + __popc(m & laneLT)] = sc;
                qn += __popc(m);
                if (qn >= 32) {
                    qn -= 32;
                    int ss = sQ[wid][qn + lane];
                    dense_eval(b * NJ + ss, yi, xi, rib, ai,
                               cai, sai, ihw, ihl, omax, amin);
                }
            }
        }
        // single drain at the end (indices are global sorted, valid throughout)
        if (lane < qn) {
            int ss = sQ[wid][lane];
            dense_eval(b * NJ + ss, yi, xi, rib, ai,
                       cai, sai, ihw, ihl, omax, amin);
        }
    }

    // intra-warp reductions
    #pragma unroll
    for (int off = 16; off; off >>= 1) {
        omax = fmaxf(omax, __shfl_xor_sync(0xffffffffu, omax, off));
        amin = fminf(amin, __shfl_xor_sync(0xffffffffu, amin, off));
    }
    if (lane == 0) { sOmax[wid] = omax; sAmin[wid] = amin; }
    __syncthreads();

    // warp-pair combine + output (sub==0 warp of each pair)
    if (sub == 0 && lane == 0 && active) {
        float fo = fmaxf(sOmax[wid], sOmax[wid + 1]);
        float fa = fminf(sAmin[wid], sAmin[wid + 1]);
        int oidx = b * P + i;
        if (oidx < out_size)
            out[oidx] = emap + fo * __ldg(comb_w + 4) + fa * __ldg(comb_w + 5);
    }
    __syncthreads();

    // ---- fused final reduction: last arriving block sums `out` ----
    if (out_size < BB * P + BB + 1) return;
    if (threadIdx.x == 0) {
        __threadfence();
        unsigned int r = atomicAdd(&g_ctr, 1u);
        sIsLast = (r == gridDim.x - 1u) ? 1u : 0u;
    }
    __syncthreads();
    if (!sIsLast) return;

    // deterministic: single block, fixed-order double accumulation
    const int gb = threadIdx.x >> 6;    // batch group (4 x 64 threads)
    const int t0 = threadIdx.x & 63;
    double s = 0.0;
    for (int t = t0; t < P; t += 64) s += (double)out[gb * P + t];
    sh[threadIdx.x] = s;
    __syncthreads();
    #pragma unroll
    for (int off = 32; off; off >>= 1) {
        if (t0 < off) sh[threadIdx.x] += sh[threadIdx.x + off];
        __syncthreads();
    }
    if (threadIdx.x == 0) {
        double tot = 0.0;
        float* outp = out + BB * P;
        for (int bb = 0; bb < BB; bb++) {
            double v = sh[bb * 64];
            outp[bb] = (float)v;
            tot += v;
        }
        outp[BB] = (float)tot;
    }
}

extern "C" void kernel_launch(void* const* d_in, const int* in_sizes, int n_in,
                              void* d_out, int out_size) {
    const float* cc  = (const float*)d_in[0];
    const int*   msk = (const int*)  d_in[1];
    const float* pem = (const float*)d_in[2];
    const float* mwm = (const float*)d_in[3];
    const float* mlm = (const float*)d_in[4];
    const float* mam = (const float*)d_in[5];
    const float* cwv = (const float*)d_in[6];
    const float* cbv = (const float*)d_in[7];
    float* out = (float*)d_out;

    // compute_context=0 -> P=1024 points/batch (out: 4096 energies + 4 per_subset + 1 total).
    // If out_size indicates the context path (pts == full 9N), use P=9216.
    int P = (out_size >= BB * NJ) ? NJ : 1024;

    prepbin_kernel<<<BB, 1024>>>(cc, msk, out, P, out_size);
    pair_kernel<<<BB * (P / IPB), 256>>>(pem, mwm, mlm, mam, cwv, cbv, out, P, out_size);
}

// round 16
// speedup vs baseline: 1.0566x; 1.0566x over previous
#include <cuda_runtime.h>
#include <math.h>

#define PI_F 3.14159265358979323846f
#define BB 4
#define NJ 9216
#define IPB 4     // i-points per block in pair (each i gets 2 warps)
#define QCAP 64   // per-warp candidate stack
#define RBMAX 21.12f        // global bound on rb = 1.3195*max(hw,hl)+1e-3, hw,hl<=16
#define NC6 6
#define NCELLS 36
#define CSZ_INV (1.0f / 43.0f)   // cell size 43 > max coarse radius 42.24

// Unsorted per-point data, preprocessed per launch.
__device__ float2 g_YX[BB * NJ];   // (y,x); invalid -> (1e9,1e9)
__device__ float2 g_RA[BB * NJ];   // (r_bound, angle)
__device__ float4 g_P2[BB * NJ];   // (cos a, sin a, 1/hw, 1/hl)
__device__ float2 g_WL[BB * NJ];   // (wv, lv) clamped
__device__ int    g_cell[BB * NJ]; // cell id or -1 if invalid

// Binning structures (valid points only, sorted by cell)
__device__ int    g_startA[BB][NCELLS + 1];
__device__ float2 g_sYX[BB * NJ];
__device__ float2 g_sRA[BB * NJ];
__device__ float4 g_sP2[BB * NJ];
__device__ int    g_iSorted[BB * NJ];   // original local index of i-points, cell-sorted
__device__ int    g_iNum[BB];
__device__ unsigned int g_ctr;          // block-arrival counter (mapred reduction)

__device__ __forceinline__ float pow10f(float x) {
    float x2 = x * x;
    float x4 = x2 * x2;
    float x8 = x4 * x4;
    return x8 * x2;
}

// t^(-0.1) via MUFU lg2/ex2
__device__ __forceinline__ float powm01f(float t) {
    float l, r;
    asm("lg2.approx.f32 %0, %1;" : "=f"(l) : "f"(t));
    l = -0.1f * l;
    asm("ex2.approx.f32 %0, %1;" : "=f"(r) : "f"(l));
    return r;
}

// prep: normalize points, compute cell id; zero out[] for invalid i-points.
__global__ void prep_kernel(const float* __restrict__ cc, const int* __restrict__ mask,
                            float* __restrict__ out, int P, int out_size) {
    int idx = blockIdx.x * blockDim.x + threadIdx.x;
    if (idx == 0) g_ctr = 0;            // reset arrival counter
    if (idx >= BB * NJ) return;
    const float* p = cc + (long)idx * 5;
    bool valid = (mask[idx] != 0);
    float y  = fminf(fmaxf(p[0], 0.f), 256.f);
    float x  = fminf(fmaxf(p[1], 0.f), 256.f);
    float wv = fminf(fmaxf(p[2], 2.f), 32.f);
    float lv = fminf(fmaxf(p[3], 2.f), 32.f);
    float a  = p[4];
    a = a - floorf(a / PI_F) * PI_F;          // jnp.mod(a, pi)
    float sa, ca;
    sincosf(a, &sa, &ca);
    float hw = 0.5f * wv, hl = 0.5f * lv;
    // superellipse p=10 radius bound: r <= 2^(1/2 - 1/10) * max(hw,hl)
    float rb = 1.3195080f * fmaxf(hw, hl) + 1e-3f;
    g_YX[idx] = valid ? make_float2(y, x) : make_float2(1e9f, 1e9f);
    g_RA[idx] = make_float2(rb, a);
    g_P2[idx] = make_float4(ca, sa, 1.f / hw, 1.f / hl);
    g_WL[idx] = make_float2(wv, lv);
    int b = idx / NJ, local = idx % NJ;
    int cellid = -1;
    if (valid) {
        int cy = min((int)(y * CSZ_INV), NC6 - 1);
        int cx = min((int)(x * CSZ_INV), NC6 - 1);
        cellid = cy * NC6 + cx;
    }
    g_cell[idx] = cellid;

    if (!valid && local < P) {
        int oidx = b * P + local;
        if (oidx < out_size) out[oidx] = 0.f;   // masked i-point: energy = 0
    }
}

// One block per batch: count (shared atomics) + prefix + scatter + i-list.
__global__ __launch_bounds__(1024) void bin_kernel(int P) {
    __shared__ int cCnt[NCELLS], iCnt[NCELLS];
    __shared__ int cStart[NCELLS + 1], cOff[NCELLS];
    __shared__ int iStart[NCELLS + 1], iOff[NCELLS];
    const int b = blockIdx.x;
    const int tid = threadIdx.x;

    if (tid < NCELLS) { cCnt[tid] = 0; iCnt[tid] = 0; cOff[tid] = 0; iOff[tid] = 0; }
    __syncthreads();

    // count
    for (int t = tid; t < NJ; t += 1024) {
        int cellid = g_cell[b * NJ + t];
        if (cellid < 0) continue;
        atomicAdd(&cCnt[cellid], 1);
        if (t < P) atomicAdd(&iCnt[cellid], 1);
    }
    __syncthreads();

    // prefix
    if (tid == 0) {
        int acc = 0, iacc = 0;
        for (int c = 0; c < NCELLS; c++) {
            cStart[c] = acc;  acc  += cCnt[c];
            iStart[c] = iacc; iacc += iCnt[c];
        }
        cStart[NCELLS] = acc;
        iStart[NCELLS] = iacc;
        g_iNum[b] = iacc;
        for (int c = 0; c <= NCELLS; c++) g_startA[b][c] = cStart[c];
    }
    __syncthreads();

    // scatter
    for (int t = tid; t < NJ; t += 1024) {
        int idx = b * NJ + t;
        int cellid = g_cell[idx];
        if (cellid < 0) continue;
        int slot = cStart[cellid] + atomicAdd(&cOff[cellid], 1);
        int gs = b * NJ + slot;
        g_sYX[gs] = g_YX[idx];
        g_sRA[gs] = g_RA[idx];
        g_sP2[gs] = g_P2[idx];
        if (t < P) {
            int islot = iStart[cellid] + atomicAdd(&iOff[cellid], 1);
            g_iSorted[b * NJ + islot] = t;
        }
    }
}

// Dense evaluation of one queued candidate (global sorted index gs).
__device__ __forceinline__ void dense_eval(
    int gs, float yi, float xi, float rib, float ai,
    float cai, float sai, float ihw, float ihl,
    float& omax, float& amin)
{
    float2 yx = g_sYX[gs];
    float2 ra = g_sRA[gs];
    float dy = yi - yx.x;
    float dx = xi - yx.y;
    float d2 = fmaf(dy, dy, dx * dx);   // > 0 guaranteed by coarse gate

    if (d2 < 1024.f) {                  // align: dist < 32 (strict)
        float ad = ai - ra.y;           // both in [0, pi)
        if (ad < 0.f) ad += PI_F;       // mod pi
        ad = fminf(ad, PI_F - ad);
        float al = fminf(fmaxf(fmaf(ad, 4.f / PI_F, -1.f), -1.f), 1.f);
        amin = fminf(amin, al);
    }

    float rsum = rib + ra.x;
    if (d2 < rsum * rsum) {             // refined overlap gate
        float d2c  = fmaxf(d2, 1e-12f);
        float rinv = rsqrtf(d2c);
        float dist = d2c * rinv;
        float ct = dy * rinv;           // cos(theta)
        float st = dx * rinv;           // sin(theta)
        float4 c2 = g_sP2[gs];
        float ci = fabsf(fmaf(ct, cai,  st * sai)) + 1e-8f;
        float si = fabsf(fmaf(st, cai, -(ct * sai))) + 1e-8f;
        float cj = fabsf(fmaf(ct, c2.x,  st * c2.y)) + 1e-8f;
        float sj = fabsf(fmaf(st, c2.x, -(ct * c2.y))) + 1e-8f;
        float ti = pow10f(ci * ihw)  + pow10f(si * ihl);
        float tj = pow10f(cj * c2.z) + pow10f(sj * c2.w);
        float ri = powm01f(ti);
        float rj = powm01f(tj);
        float ov = 1.f - __fdividef(dist, ri + rj + 1e-8f);
        omax = fmaxf(omax, fminf(fmaxf(ov, 0.f), 1.f));
    }
}

// 2 warps per i-point (R11 configuration). Writes overlap/align terms only.
__global__ __launch_bounds__(256) void pair_kernel(
    const float* __restrict__ comb_w,
    float* __restrict__ out, int P, int out_size)
{
    __shared__ int   sQ[8][QCAP];
    __shared__ float sOmax[8], sAmin[8];

    const int bpb  = P / IPB;
    const int b    = blockIdx.x / bpb;
    const int wid  = threadIdx.x >> 5;
    const int sub  = wid & 1;                              // which half of the chunks
    const int k    = (blockIdx.x % bpb) * IPB + (wid >> 1);  // sorted i index
    const int lane = threadIdx.x & 31;
    const unsigned laneLT = (1u << lane) - 1u;

    const bool active = (k < g_iNum[b]);
    float yi = 0.f, xi = 0.f, rib = 0.f, ai = 0.f;
    float cai = 1.f, sai = 0.f, ihw = 1.f, ihl = 1.f;
    float coarse2 = 0.f;
    int   i = 0;

    if (active) {
        i = g_iSorted[b * NJ + k];
        int gi = b * NJ + i;
        float2 yx1 = g_YX[gi];
        float2 ra1 = g_RA[gi];
        float4 p2  = g_P2[gi];
        yi = yx1.x; xi = yx1.y; rib = ra1.x; ai = ra1.y;
        cai = p2.x; sai = p2.y; ihw = p2.z; ihl = p2.w;
        float cr = rib + RBMAX;
        coarse2 = fmaxf(cr * cr, 1024.f);
    }

    float omax = 0.f;   // overlap contributions are >= 0; self/invalid give 0
    float amin = 0.f;   // align matrix always contains 0 entries (self pair)
    int   qn   = 0;     // per-warp candidate-stack depth (warp-uniform)

    if (active) {
        int cy = min((int)(yi * CSZ_INV), NC6 - 1);
        int cx = min((int)(xi * CSZ_INV), NC6 - 1);
        int r0 = max(cy - 1, 0), r1 = min(cy + 1, NC6 - 1);
        int c0 = max(cx - 1, 0), c1 = min(cx + 1, NC6 - 1);

        for (int row = r0; row <= r1; row++) {
            // cells row*6+c0 .. row*6+c1 are contiguous -> single range
            int lo = g_startA[b][row * NC6 + c0];
            int hi = g_startA[b][row * NC6 + c1 + 1];
            for (int base = lo + sub * 32; base < hi; base += 64) {
                int s = base + lane;
                int sc = min(s, hi - 1);              // clamp load, gate with (s<hi)
                float2 q = g_sYX[b * NJ + sc];
                float dy = yi - q.x;
                float dx = xi - q.y;
                float d2 = fmaf(dy, dy, dx * dx);
                bool cand = (s < hi) && (d2 > 0.f) && (d2 < coarse2);

                unsigned m = __ballot_sync(0xffffffffu, cand);
                if (cand) sQ[wid][qn + __popc(m & laneLT)] = sc;
                qn += __popc(m);
                if (qn >= 32) {
                    qn -= 32;
                    int ss = sQ[wid][qn + lane];
                    dense_eval(b * NJ + ss, yi, xi, rib, ai,
                               cai, sai, ihw, ihl, omax, amin);
                }
            }
        }
        // single drain at the end (indices are global sorted, valid throughout)
        if (lane < qn) {
            int ss = sQ[wid][lane];
            dense_eval(b * NJ + ss, yi, xi, rib, ai,
                       cai, sai, ihw, ihl, omax, amin);
        }
    }

    // intra-warp reductions
    #pragma unroll
    for (int off = 16; off; off >>= 1) {
        omax = fmaxf(omax, __shfl_xor_sync(0xffffffffu, omax, off));
        amin = fminf(amin, __shfl_xor_sync(0xffffffffu, amin, off));
    }
    if (lane == 0) { sOmax[wid] = omax; sAmin[wid] = amin; }
    __syncthreads();

    // warp-pair combine + output (sub==0 warp of each pair)
    if (sub == 0 && lane == 0 && active) {
        float fo = fmaxf(sOmax[wid], sOmax[wid + 1]);
        float fa = fminf(sAmin[wid], sAmin[wid + 1]);
        int oidx = b * P + i;
        if (oidx < out_size)
            out[oidx] = fo * comb_w[4] + fa * comb_w[5];
    }
}

// mapred: one warp per valid i-point, lane-parallel map gathers (out += emap);
// last arriving block performs the deterministic per-batch/total reduction.
__global__ __launch_bounds__(256) void mapred_kernel(
    const float* __restrict__ pem, const float* __restrict__ mwm,
    const float* __restrict__ mlm, const float* __restrict__ mam,
    const float* __restrict__ comb_w, const float* __restrict__ comb_b,
    float* __restrict__ out, int P, int out_size)
{
    __shared__ unsigned int sIsLast;
    __shared__ double sh[256];

    const int wpb  = 8;                 // warps per block
    const int bpb  = P / wpb;
    const int b    = blockIdx.x / bpb;
    const int wid  = threadIdx.x >> 5;
    const int k    = (blockIdx.x % bpb) * wpb + wid;
    const int lane = threadIdx.x & 31;

    const bool active = (k < g_iNum[b]);
    if (active) {
        int i  = g_iSorted[b * NJ + k];
        int gi = b * NJ + i;
        float2 yx1 = g_YX[gi];
        float2 wl  = g_WL[gi];
        float ai   = g_RA[gi].y;
        float yi = yx1.x, xi = yx1.y;

        float val = 0.f;
        float yc = fminf(yi, 255.f);           // yi,xi in [0,256]
        float xc = fminf(xi, 255.f);
        float y0 = floorf(yc), x0 = floorf(xc);
        int iy0 = (int)y0, ix0 = (int)x0;
        int iy1 = min(iy0 + 1, 255), ix1 = min(ix0 + 1, 255);
        float wy = yc - y0, wx = xc - x0;
        if (lane < 28) {
            int t = (lane < 4) ? 0 : ((lane < 12) ? 1 : ((lane < 20) ? 2 : 3));
            int rel = (t == 0) ? lane : (lane - 4 - (t - 1) * 8);
            int ch  = (t == 0) ? 0 : (rel >> 2);
            int corner = rel & 3;
            int iy = (corner & 2) ? iy1 : iy0;
            int ix = (corner & 1) ? ix1 : ix0;
            float wgt = ((corner & 2) ? wy : 1.f - wy) * ((corner & 1) ? wx : 1.f - wx);
            const float* mp;
            float m;
            if      (t == 0) { mp = pem; m = 0.f;   }
            else if (t == 1) { mp = mwm; m = wl.x;  }
            else if (t == 2) { mp = mlm; m = wl.y;  }
            else             { mp = mam; m = ai;    }
            int cidx = 0;
            if (t == 3) {                       // cyclic trilinear, vmin=0 vmax=pi
                float c = (m - 0.f) / PI_F * 32.f - 0.5f;
                c = c - floorf(c * (1.f / 32.f)) * 32.f;
                float c0 = floorf(c);
                float cw = c - c0;
                int i0 = ((int)c0) & 31, i1 = (i0 + 1) & 31;
                cidx = ch ? i1 : i0;
                wgt *= ch ? cw : 1.f - cw;
            } else if (t > 0) {                 // non-cyclic, vmin=2 vmax=32
                float c = (m - 2.f) / 30.f * 32.f - 0.5f;
                c = fminf(fmaxf(c, 0.f), 31.f);
                float c0 = floorf(c);
                float cw = c - c0;
                int i0 = (int)c0, i1 = min(i0 + 1, 31);
                cidx = ch ? i1 : i0;
                wgt *= ch ? cw : 1.f - cw;
            }
            val = __ldg(mp + cidx * 65536 + iy * 256 + ix) * wgt * __ldg(comb_w + t);
        } else if (lane == 28) {
            float area = 1.f - 2.f * fminf(fmaxf(wl.x * wl.y * (1.f / 256.f), 0.f), 1.f);
            val = area * __ldg(comb_w + 6) + __ldg(comb_b);
        }
        #pragma unroll
        for (int off = 16; off; off >>= 1)
            val += __shfl_xor_sync(0xffffffffu, val, off);
        if (lane == 0) {
            int oidx = b * P + i;
            if (oidx < out_size) out[oidx] += val;
        }
    }
    __syncthreads();

    // ---- fused final reduction: last arriving block sums `out` ----
    if (out_size < BB * P + BB + 1) return;
    if (threadIdx.x == 0) {
        __threadfence();
        unsigned int r = atomicAdd(&g_ctr, 1u);
        sIsLast = (r == gridDim.x - 1u) ? 1u : 0u;
    }
    __syncthreads();
    if (!sIsLast) return;

    // deterministic: single block, fixed-order double accumulation
    const int gb = threadIdx.x >> 6;    // batch group (4 x 64 threads)
    const int t0 = threadIdx.x & 63;
    double s = 0.0;
    for (int t = t0; t < P; t += 64) s += (double)out[gb * P + t];
    sh[threadIdx.x] = s;
    __syncthreads();
    #pragma unroll
    for (int off = 32; off; off >>= 1) {
        if (t0 < off) sh[threadIdx.x] += sh[threadIdx.x + off];
        __syncthreads();
    }
    if (threadIdx.x == 0) {
        double tot = 0.0;
        float* outp = out + BB * P;
        for (int bb = 0; bb < BB; bb++) {
            double v = sh[bb * 64];
            outp[bb] = (float)v;
            tot += v;
        }
        outp[BB] = (float)tot;
    }
}

extern "C" void kernel_launch(void* const* d_in, const int* in_sizes, int n_in,
                              void* d_out, int out_size) {
    const float* cc  = (const float*)d_in[0];
    const int*   msk = (const int*)  d_in[1];
    const float* pem = (const float*)d_in[2];
    const float* mwm = (const float*)d_in[3];
    const float* mlm = (const float*)d_in[4];
    const float* mam = (const float*)d_in[5];
    const float* cwv = (const float*)d_in[6];
    const float* cbv = (const float*)d_in[7];
    float* out = (float*)d_out;

    // compute_context=0 -> P=1024 points/batch (out: 4096 energies + 4 per_subset + 1 total).
    // If out_size indicates the context path (pts == full 9N), use P=9216.
    int P = (out_size >= BB * NJ) ? NJ : 1024;

    prep_kernel<<<(BB * NJ + 255) / 256, 256>>>(cc, msk, out, P, out_size);
    bin_kernel<<<BB, 1024>>>(P);
    pair_kernel<<<BB * (P / IPB), 256>>>(cwv, out, P, out_size);
    mapred_kernel<<<BB * (P / 8), 256>>>(pem, mwm, mlm, mam, cwv, cbv, out, P, out_size);
}

// round 17
// speedup vs baseline: 1.1123x; 1.0527x over previous
#include <cuda_runtime.h>
#include <math.h>

#define PI_F 3.14159265358979323846f
#define BB 4
#define NJ 9216
#define IPB 4     // i-points per pair-role block (each i gets 2 warps)
#define QCAP 64   // per-warp candidate stack
#define RBMAX 21.12f        // global bound on rb = 1.3195*max(hw,hl)+1e-3, hw,hl<=16
#define NC6 6
#define NCELLS 36
#define CSZ_INV (1.0f / 43.0f)   // cell size 43 > max coarse radius 42.24

// Unsorted per-point data, preprocessed per launch.
__device__ float2 g_YX[BB * NJ];   // (y,x); invalid -> (1e9,1e9)
__device__ float2 g_RA[BB * NJ];   // (r_bound, angle)
__device__ float4 g_P2[BB * NJ];   // (cos a, sin a, 1/hw, 1/hl)
__device__ float2 g_WL[BB * NJ];   // (wv, lv) clamped
__device__ int    g_cell[BB * NJ]; // cell id or -1 if invalid

// Binning structures (valid points only, sorted by cell)
__device__ int    g_startA[BB][NCELLS + 1];
__device__ float2 g_sYX[BB * NJ];
__device__ float2 g_sRA[BB * NJ];
__device__ float4 g_sP2[BB * NJ];
__device__ int    g_iSorted[BB * NJ];   // original local index of i-points, cell-sorted
__device__ int    g_iNum[BB];
__device__ unsigned int g_ctr;          // block-arrival counter (fused reduction)

__device__ __forceinline__ float pow10f(float x) {
    float x2 = x * x;
    float x4 = x2 * x2;
    float x8 = x4 * x4;
    return x8 * x2;
}

// t^(-0.1) via MUFU lg2/ex2
__device__ __forceinline__ float powm01f(float t) {
    float l, r;
    asm("lg2.approx.f32 %0, %1;" : "=f"(l) : "f"(t));
    l = -0.1f * l;
    asm("ex2.approx.f32 %0, %1;" : "=f"(r) : "f"(l));
    return r;
}

// prep: normalize points, compute cell id; zero out[] for ALL i-points.
__global__ void prep_kernel(const float* __restrict__ cc, const int* __restrict__ mask,
                            float* __restrict__ out, int P, int out_size) {
    int idx = blockIdx.x * blockDim.x + threadIdx.x;
    if (idx == 0) g_ctr = 0;            // reset arrival counter
    if (idx >= BB * NJ) return;
    const float* p = cc + (long)idx * 5;
    bool valid = (mask[idx] != 0);
    float y  = fminf(fmaxf(p[0], 0.f), 256.f);
    float x  = fminf(fmaxf(p[1], 0.f), 256.f);
    float wv = fminf(fmaxf(p[2], 2.f), 32.f);
    float lv = fminf(fmaxf(p[3], 2.f), 32.f);
    float a  = p[4];
    a = a - floorf(a / PI_F) * PI_F;          // jnp.mod(a, pi)
    float sa, ca;
    sincosf(a, &sa, &ca);
    float hw = 0.5f * wv, hl = 0.5f * lv;
    // superellipse p=10 radius bound: r <= 2^(1/2 - 1/10) * max(hw,hl)
    float rb = 1.3195080f * fmaxf(hw, hl) + 1e-3f;
    g_YX[idx] = valid ? make_float2(y, x) : make_float2(1e9f, 1e9f);
    g_RA[idx] = make_float2(rb, a);
    g_P2[idx] = make_float4(ca, sa, 1.f / hw, 1.f / hl);
    g_WL[idx] = make_float2(wv, lv);
    int b = idx / NJ, local = idx % NJ;
    int cellid = -1;
    if (valid) {
        int cy = min((int)(y * CSZ_INV), NC6 - 1);
        int cx = min((int)(x * CSZ_INV), NC6 - 1);
        cellid = cy * NC6 + cx;
    }
    g_cell[idx] = cellid;

    if (local < P) {
        int oidx = b * P + local;
        if (oidx < out_size) out[oidx] = 0.f;   // both roles accumulate via atomicAdd
    }
}

// One block per batch: count (shared atomics) + prefix + scatter + i-list.
__global__ __launch_bounds__(1024) void bin_kernel(int P) {
    __shared__ int cCnt[NCELLS], iCnt[NCELLS];
    __shared__ int cStart[NCELLS + 1], cOff[NCELLS];
    __shared__ int iStart[NCELLS + 1], iOff[NCELLS];
    const int b = blockIdx.x;
    const int tid = threadIdx.x;

    if (tid < NCELLS) { cCnt[tid] = 0; iCnt[tid] = 0; cOff[tid] = 0; iOff[tid] = 0; }
    __syncthreads();

    // count
    for (int t = tid; t < NJ; t += 1024) {
        int cellid = g_cell[b * NJ + t];
        if (cellid < 0) continue;
        atomicAdd(&cCnt[cellid], 1);
        if (t < P) atomicAdd(&iCnt[cellid], 1);
    }
    __syncthreads();

    // prefix
    if (tid == 0) {
        int acc = 0, iacc = 0;
        for (int c = 0; c < NCELLS; c++) {
            cStart[c] = acc;  acc  += cCnt[c];
            iStart[c] = iacc; iacc += iCnt[c];
        }
        cStart[NCELLS] = acc;
        iStart[NCELLS] = iacc;
        g_iNum[b] = iacc;
        for (int c = 0; c <= NCELLS; c++) g_startA[b][c] = cStart[c];
    }
    __syncthreads();

    // scatter
    for (int t = tid; t < NJ; t += 1024) {
        int idx = b * NJ + t;
        int cellid = g_cell[idx];
        if (cellid < 0) continue;
        int slot = cStart[cellid] + atomicAdd(&cOff[cellid], 1);
        int gs = b * NJ + slot;
        g_sYX[gs] = g_YX[idx];
        g_sRA[gs] = g_RA[idx];
        g_sP2[gs] = g_P2[idx];
        if (t < P) {
            int islot = iStart[cellid] + atomicAdd(&iOff[cellid], 1);
            g_iSorted[b * NJ + islot] = t;
        }
    }
}

// Dense evaluation of one queued candidate (global sorted index gs).
__device__ __forceinline__ void dense_eval(
    int gs, float yi, float xi, float rib, float ai,
    float cai, float sai, float ihw, float ihl,
    float& omax, float& amin)
{
    float2 yx = g_sYX[gs];
    float2 ra = g_sRA[gs];
    float dy = yi - yx.x;
    float dx = xi - yx.y;
    float d2 = fmaf(dy, dy, dx * dx);   // > 0 guaranteed by coarse gate

    if (d2 < 1024.f) {                  // align: dist < 32 (strict)
        float ad = ai - ra.y;           // both in [0, pi)
        if (ad < 0.f) ad += PI_F;       // mod pi
        ad = fminf(ad, PI_F - ad);
        float al = fminf(fmaxf(fmaf(ad, 4.f / PI_F, -1.f), -1.f), 1.f);
        amin = fminf(amin, al);
    }

    float rsum = rib + ra.x;
    if (d2 < rsum * rsum) {             // refined overlap gate
        float d2c  = fmaxf(d2, 1e-12f);
        float rinv = rsqrtf(d2c);
        float dist = d2c * rinv;
        float ct = dy * rinv;           // cos(theta)
        float st = dx * rinv;           // sin(theta)
        float4 c2 = g_sP2[gs];
        float ci = fabsf(fmaf(ct, cai,  st * sai)) + 1e-8f;
        float si = fabsf(fmaf(st, cai, -(ct * sai))) + 1e-8f;
        float cj = fabsf(fmaf(ct, c2.x,  st * c2.y)) + 1e-8f;
        float sj = fabsf(fmaf(st, c2.x, -(ct * c2.y))) + 1e-8f;
        float ti = pow10f(ci * ihw)  + pow10f(si * ihl);
        float tj = pow10f(cj * c2.z) + pow10f(sj * c2.w);
        float ri = powm01f(ti);
        float rj = powm01f(tj);
        float ov = 1.f - __fdividef(dist, ri + rj + 1e-8f);
        omax = fmaxf(omax, fminf(fmaxf(ov, 0.f), 1.f));
    }
}

// Mega kernel: blocks [0, pairB) do pair work (2 warps per i); blocks
// [pairB, pairB+mapB) do lane-parallel map gathers (1 warp per i).
// Each role contributes its energy terms via ONE atomicAdd per point
// (exactly two commutative adds onto 0 -> deterministic). Last arriving
// block performs the fixed-order per-batch/total reduction.
__global__ __launch_bounds__(256) void mega_kernel(
    const float* __restrict__ pem, const float* __restrict__ mwm,
    const float* __restrict__ mlm, const float* __restrict__ mam,
    const float* __restrict__ comb_w, const float* __restrict__ comb_b,
    float* __restrict__ out, int P, int out_size, int pairB)
{
    __shared__ int   sQ[8][QCAP];
    __shared__ float sOmax[8], sAmin[8];
    __shared__ unsigned int sIsLast;
    __shared__ double sh[256];

    const int wid  = threadIdx.x >> 5;
    const int lane = threadIdx.x & 31;

    if ((int)blockIdx.x < pairB) {
        // ---------------- pair role ----------------
        const int bpb  = P / IPB;
        const int b    = blockIdx.x / bpb;
        const int sub  = wid & 1;                              // which half of the chunks
        const int k    = (blockIdx.x % bpb) * IPB + (wid >> 1);  // sorted i index
        const unsigned laneLT = (1u << lane) - 1u;

        const bool active = (k < g_iNum[b]);
        float yi = 0.f, xi = 0.f, rib = 0.f, ai = 0.f;
        float cai = 1.f, sai = 0.f, ihw = 1.f, ihl = 1.f;
        float coarse2 = 0.f;
        int   i = 0;

        if (active) {
            i = g_iSorted[b * NJ + k];
            int gi = b * NJ + i;
            float2 yx1 = g_YX[gi];
            float2 ra1 = g_RA[gi];
            float4 p2  = g_P2[gi];
            yi = yx1.x; xi = yx1.y; rib = ra1.x; ai = ra1.y;
            cai = p2.x; sai = p2.y; ihw = p2.z; ihl = p2.w;
            float cr = rib + RBMAX;
            coarse2 = fmaxf(cr * cr, 1024.f);
        }

        float omax = 0.f;   // overlap contributions are >= 0; self/invalid give 0
        float amin = 0.f;   // align matrix always contains 0 entries (self pair)
        int   qn   = 0;     // per-warp candidate-stack depth (warp-uniform)

        if (active) {
            int cy = min((int)(yi * CSZ_INV), NC6 - 1);
            int cx = min((int)(xi * CSZ_INV), NC6 - 1);
            int r0 = max(cy - 1, 0), r1 = min(cy + 1, NC6 - 1);
            int c0 = max(cx - 1, 0), c1 = min(cx + 1, NC6 - 1);

            for (int row = r0; row <= r1; row++) {
                // cells row*6+c0 .. row*6+c1 are contiguous -> single range
                int lo = g_startA[b][row * NC6 + c0];
                int hi = g_startA[b][row * NC6 + c1 + 1];
                for (int base = lo + sub * 32; base < hi; base += 64) {
                    int s = base + lane;
                    int sc = min(s, hi - 1);              // clamp load, gate with (s<hi)
                    float2 q = g_sYX[b * NJ + sc];
                    float dy = yi - q.x;
                    float dx = xi - q.y;
                    float d2 = fmaf(dy, dy, dx * dx);
                    bool cand = (s < hi) && (d2 > 0.f) && (d2 < coarse2);

                    unsigned m = __ballot_sync(0xffffffffu, cand);
                    if (cand) sQ[wid][qn + __popc(m & laneLT)] = sc;
                    qn += __popc(m);
                    if (qn >= 32) {
                        qn -= 32;
                        int ss = sQ[wid][qn + lane];
                        dense_eval(b * NJ + ss, yi, xi, rib, ai,
                                   cai, sai, ihw, ihl, omax, amin);
                    }
                }
            }
            // single drain at the end (indices are global sorted, valid throughout)
            if (lane < qn) {
                int ss = sQ[wid][lane];
                dense_eval(b * NJ + ss, yi, xi, rib, ai,
                           cai, sai, ihw, ihl, omax, amin);
            }
        }

        // intra-warp reductions
        #pragma unroll
        for (int off = 16; off; off >>= 1) {
            omax = fmaxf(omax, __shfl_xor_sync(0xffffffffu, omax, off));
            amin = fminf(amin, __shfl_xor_sync(0xffffffffu, amin, off));
        }
        if (lane == 0) { sOmax[wid] = omax; sAmin[wid] = amin; }
        __syncthreads();

        // warp-pair combine + accumulate (sub==0 warp of each pair)
        if (sub == 0 && lane == 0 && active) {
            float fo = fmaxf(sOmax[wid], sOmax[wid + 1]);
            float fa = fminf(sAmin[wid], sAmin[wid + 1]);
            int oidx = b * P + i;
            if (oidx < out_size)
                atomicAdd(out + oidx, fo * comb_w[4] + fa * comb_w[5]);
        }
    } else {
        // ---------------- map role ----------------
        const int mb   = blockIdx.x - pairB;
        const int wpb  = 8;
        const int bpb  = P / wpb;
        const int b    = mb / bpb;
        const int i    = (mb % bpb) * wpb + wid;   // raw local i-point index
        const int gi   = b * NJ + i;

        if (i < P && g_YX[gi].x < 1e8f) {          // valid point
            float2 yx1 = g_YX[gi];
            float2 wl  = g_WL[gi];
            float ai   = g_RA[gi].y;
            float yi = yx1.x, xi = yx1.y;

            float val = 0.f;
            float yc = fminf(yi, 255.f);           // yi,xi in [0,256]
            float xc = fminf(xi, 255.f);
            float y0 = floorf(yc), x0 = floorf(xc);
            int iy0 = (int)y0, ix0 = (int)x0;
            int iy1 = min(iy0 + 1, 255), ix1 = min(ix0 + 1, 255);
            float wy = yc - y0, wx = xc - x0;
            if (lane < 28) {
                int t = (lane < 4) ? 0 : ((lane < 12) ? 1 : ((lane < 20) ? 2 : 3));
                int rel = (t == 0) ? lane : (lane - 4 - (t - 1) * 8);
                int ch  = (t == 0) ? 0 : (rel >> 2);
                int corner = rel & 3;
                int iy = (corner & 2) ? iy1 : iy0;
                int ix = (corner & 1) ? ix1 : ix0;
                float wgt = ((corner & 2) ? wy : 1.f - wy) * ((corner & 1) ? wx : 1.f - wx);
                const float* mp;
                float m;
                if      (t == 0) { mp = pem; m = 0.f;   }
                else if (t == 1) { mp = mwm; m = wl.x;  }
                else if (t == 2) { mp = mlm; m = wl.y;  }
                else             { mp = mam; m = ai;    }
                int cidx = 0;
                if (t == 3) {                       // cyclic trilinear, vmin=0 vmax=pi
                    float c = (m - 0.f) / PI_F * 32.f - 0.5f;
                    c = c - floorf(c * (1.f / 32.f)) * 32.f;
                    float c0 = floorf(c);
                    float cw = c - c0;
                    int i0 = ((int)c0) & 31, i1 = (i0 + 1) & 31;
                    cidx = ch ? i1 : i0;
                    wgt *= ch ? cw : 1.f - cw;
                } else if (t > 0) {                 // non-cyclic, vmin=2 vmax=32
                    float c = (m - 2.f) / 30.f * 32.f - 0.5f;
                    c = fminf(fmaxf(c, 0.f), 31.f);
                    float c0 = floorf(c);
                    float cw = c - c0;
                    int i0 = (int)c0, i1 = min(i0 + 1, 31);
                    cidx = ch ? i1 : i0;
                    wgt *= ch ? cw : 1.f - cw;
                }
                val = __ldg(mp + cidx * 65536 + iy * 256 + ix) * wgt * __ldg(comb_w + t);
            } else if (lane == 28) {
                float area = 1.f - 2.f * fminf(fmaxf(wl.x * wl.y * (1.f / 256.f), 0.f), 1.f);
                val = area * __ldg(comb_w + 6) + __ldg(comb_b);
            }
            #pragma unroll
            for (int off = 16; off; off >>= 1)
                val += __shfl_xor_sync(0xffffffffu, val, off);
            if (lane == 0) {
                int oidx = b * P + i;
                if (oidx < out_size) atomicAdd(out + oidx, val);
            }
        }
        __syncthreads();
    }

    // ---- fused final reduction: last arriving block sums `out` ----
    if (out_size < BB * P + BB + 1) return;
    if (threadIdx.x == 0) {
        __threadfence();
        unsigned int r = atomicAdd(&g_ctr, 1u);
        sIsLast = (r == gridDim.x - 1u) ? 1u : 0u;
    }
    __syncthreads();
    if (!sIsLast) return;

    // deterministic: single block, fixed-order double accumulation
    const int gb = threadIdx.x >> 6;    // batch group (4 x 64 threads)
    const int t0 = threadIdx.x & 63;
    double s = 0.0;
    for (int t = t0; t < P; t += 64) s += (double)out[gb * P + t];
    sh[threadIdx.x] = s;
    __syncthreads();
    #pragma unroll
    for (int off = 32; off; off >>= 1) {
        if (t0 < off) sh[threadIdx.x] += sh[threadIdx.x + off];
        __syncthreads();
    }
    if (threadIdx.x == 0) {
        double tot = 0.0;
        float* outp = out + BB * P;
        for (int bb = 0; bb < BB; bb++) {
            double v = sh[bb * 64];
            outp[bb] = (float)v;
            tot += v;
        }
        outp[BB] = (float)tot;
    }
}

extern "C" void kernel_launch(void* const* d_in, const int* in_sizes, int n_in,
                              void* d_out, int out_size) {
    const float* cc  = (const float*)d_in[0];
    const int*   msk = (const int*)  d_in[1];
    const float* pem = (const float*)d_in[2];
    const float* mwm = (const float*)d_in[3];
    const float* mlm = (const float*)d_in[4];
    const float* mam = (const float*)d_in[5];
    const float* cwv = (const float*)d_in[6];
    const float* cbv = (const float*)d_in[7];
    float* out = (float*)d_out;

    // compute_context=0 -> P=1024 points/batch (out: 4096 energies + 4 per_subset + 1 total).
    // If out_size indicates the context path (pts == full 9N), use P=9216.
    int P = (out_size >= BB * NJ) ? NJ : 1024;

    int pairB = BB * (P / IPB);
    int mapB  = BB * (P / 8);

    prep_kernel<<<(BB * NJ + 255) / 256, 256>>>(cc, msk, out, P, out_size);
    bin_kernel<<<BB, 1024>>>(P);
    mega_kernel<<<pairB + mapB, 256>>>(pem, mwm, mlm, mam, cwv, cbv,
                                       out, P, out_size, pairB);
}